// round 3
// baseline (speedup 1.0000x reference)
#include <cuda_runtime.h>
#include <math.h>

// ---------------------------------------------------------------------------
// LocalSparseAttention (Swin-style windowed attention)
//   B=2, N=65536 (256x256), C=256, window=16 (256 tokens/window), heads=8, hd=32
//   Pipeline: QKV GEMM -> per-(window,head) attention (+attn output) -> proj GEMM
// ---------------------------------------------------------------------------

#define MROWS 131072L   // B*N = 2*65536 tokens
#define CDIM  256
#define QKVN  768
#define NWIN  512       // B * (256/16)^2
#define NHEAD 8
#define HDIM  32

static const long OUT_ELEMS  = MROWS * CDIM;            // 33,554,432
static const long ATTN_ELEMS = (long)NWIN * NHEAD * 256 * 256; // 268,435,456

// Scratch (static __device__ arrays: allocation-free per harness rules)
__device__ float g_qkv[MROWS * QKVN];   // [token, 768] = [q|k|v], head-major 32-chunks
__device__ float g_o  [MROWS * CDIM];   // attention output, token-major

// ---------------------------------------------------------------------------
// Classic 128x128x8 fp32 register-tiled GEMM with bias.
//   C[M,N] = A[M,K] @ B[K,N] + bias[N]
//   M = gridDim.y*128 (all dims divisible by tiles; no bounds checks needed)
// ---------------------------------------------------------------------------
__global__ __launch_bounds__(256, 2)
void sgemm_bias(const float* __restrict__ A, const float* __restrict__ B,
                const float* __restrict__ bias, float* __restrict__ C,
                int N, int K)
{
    __shared__ float As[8][132];   // A tile transposed, padded (bank-conflict-free)
    __shared__ float Bs[8][128];

    const int tid = threadIdx.x;
    const int bm = blockIdx.y * 128;
    const int bn = blockIdx.x * 128;

    // A tile load: 128 rows x 8 cols, one float4 per thread
    const int arow = tid >> 1;
    const int ac4  = (tid & 1) * 4;
    // B tile load: 8 rows x 128 cols
    const int brow = tid >> 5;
    const int bc4  = (tid & 31) * 4;

    const float* Ag = A + (long)(bm + arow) * K + ac4;
    const float* Bg = B + (long)brow * N + bn + bc4;

    // Compute mapping: thread covers rows {tr..tr+3, tr+64..tr+67}, cols likewise
    const int tr = (tid >> 4) * 4;
    const int tc = (tid & 15) * 4;

    float acc[8][8];
#pragma unroll
    for (int i = 0; i < 8; i++)
#pragma unroll
        for (int j = 0; j < 8; j++) acc[i][j] = 0.f;

    for (int kt = 0; kt < K; kt += 8) {
        float4 av = *(const float4*)(Ag + kt);
        float4 bv = *(const float4*)(Bg + (long)kt * N);
        As[ac4 + 0][arow] = av.x;
        As[ac4 + 1][arow] = av.y;
        As[ac4 + 2][arow] = av.z;
        As[ac4 + 3][arow] = av.w;
        *(float4*)(&Bs[brow][bc4]) = bv;
        __syncthreads();

#pragma unroll
        for (int kk = 0; kk < 8; kk++) {
            float a[8], b[8];
            *(float4*)(a)     = *(const float4*)(&As[kk][tr]);
            *(float4*)(a + 4) = *(const float4*)(&As[kk][tr + 64]);
            *(float4*)(b)     = *(const float4*)(&Bs[kk][tc]);
            *(float4*)(b + 4) = *(const float4*)(&Bs[kk][tc + 64]);
#pragma unroll
            for (int i = 0; i < 8; i++)
#pragma unroll
                for (int j = 0; j < 8; j++)
                    acc[i][j] += a[i] * b[j];
        }
        __syncthreads();
    }

    // Epilogue: bias + store (two float4 per row)
    float bs0[4], bs1[4];
#pragma unroll
    for (int j = 0; j < 4; j++) {
        bs0[j] = bias[bn + tc + j];
        bs1[j] = bias[bn + 64 + tc + j];
    }
#pragma unroll
    for (int i = 0; i < 8; i++) {
        int row = bm + ((i < 4) ? (tr + i) : (64 + tr + i - 4));
        float* Crow = C + (long)row * N + bn;
        float4 o0, o1;
        o0.x = acc[i][0] + bs0[0]; o0.y = acc[i][1] + bs0[1];
        o0.z = acc[i][2] + bs0[2]; o0.w = acc[i][3] + bs0[3];
        o1.x = acc[i][4] + bs1[0]; o1.y = acc[i][5] + bs1[1];
        o1.z = acc[i][6] + bs1[2]; o1.w = acc[i][7] + bs1[3];
        *(float4*)(Crow + tc)      = o0;
        *(float4*)(Crow + 64 + tc) = o1;
    }
}

// ---------------------------------------------------------------------------
// Windowed attention: one block per (window, head). 256 threads = 8 warps.
//   Q: [256,32] smem (broadcast reads), K: [256,36-padded] (conflict-free LDS.128),
//   V: transposed [32, 268-padded] (per-lane float4 dot), P staged per-warp.
//   Warp w handles query rows w, w+8, ..., w+248.
// ---------------------------------------------------------------------------
#define SM_Q   0                 // 256*32   = 8192 floats
#define SM_K   8192              // 256*36   = 9216 floats
#define SM_V   17408             // 32*268   = 8576 floats
#define SM_P   25984             // 8*256    = 2048 floats
#define SM_FLOATS 28032
#define SM_BYTES (SM_FLOATS * 4)

__global__ __launch_bounds__(256, 2)
void attn_kernel(const float* __restrict__ qkv, float* __restrict__ o_out,
                 float* __restrict__ attn)
{
    extern __shared__ float sm[];
    float* qs  = sm + SM_Q;
    float* ks  = sm + SM_K;
    float* vst = sm + SM_V;
    float* prw = sm + SM_P;

    const int bid = blockIdx.x;        // 0..4095
    const int win = bid >> 3;          // 0..511 (b, win_y, win_x)
    const int h   = bid & 7;
    const int b     = win >> 8;
    const int win_y = (win >> 4) & 15;
    const int win_x = win & 15;

    const int tw = threadIdx.x;        // token-in-window for loading
    {
        const int wy = tw >> 4, wx = tw & 15;
        const long g = (long)b * 65536 + (long)(win_y * 16 + wy) * 256 + (win_x * 16 + wx);
        const float4* src = (const float4*)(qkv + g * QKVN + h * HDIM);
#pragma unroll
        for (int d4 = 0; d4 < 8; d4++) {
            float4 qv = src[d4];        // q chunk
            float4 kv = src[64 + d4];   // +256 floats
            float4 vv = src[128 + d4];  // +512 floats
            ((float4*)(qs + tw * 32))[d4] = qv;
            ((float4*)(ks + tw * 36))[d4] = kv;
            vst[(d4 * 4 + 0) * 268 + tw] = vv.x;
            vst[(d4 * 4 + 1) * 268 + tw] = vv.y;
            vst[(d4 * 4 + 2) * 268 + tw] = vv.z;
            vst[(d4 * 4 + 3) * 268 + tw] = vv.w;
        }
    }
    __syncthreads();

    const int lane = tw & 31;
    const int w    = tw >> 5;
    float* pr = prw + w * 256;
    const float scale = 0.17677669529663687f;  // 32^-0.5
    const long attn_head_base = ((long)win * NHEAD + h) * 256 * 256;

    for (int qr = w; qr < 256; qr += 8) {
        // ---- S row: s[j] for j = jj*32+lane ----
        const float4* q4 = (const float4*)(qs + qr * 32);
        float s[8];
#pragma unroll
        for (int jj = 0; jj < 8; jj++) s[jj] = 0.f;
#pragma unroll
        for (int d4 = 0; d4 < 8; d4++) {
            float4 qv = q4[d4];   // broadcast
#pragma unroll
            for (int jj = 0; jj < 8; jj++) {
                float4 kv = ((const float4*)(ks + (jj * 32 + lane) * 36))[d4];
                s[jj] += qv.x * kv.x + qv.y * kv.y + qv.z * kv.z + qv.w * kv.w;
            }
        }
#pragma unroll
        for (int jj = 0; jj < 8; jj++) s[jj] *= scale;

        // ---- softmax (warp-wide over 256 values) ----
        float m = s[0];
#pragma unroll
        for (int jj = 1; jj < 8; jj++) m = fmaxf(m, s[jj]);
#pragma unroll
        for (int off = 16; off > 0; off >>= 1)
            m = fmaxf(m, __shfl_xor_sync(0xffffffffu, m, off));
        float e[8], l = 0.f;
#pragma unroll
        for (int jj = 0; jj < 8; jj++) { e[jj] = __expf(s[jj] - m); l += e[jj]; }
#pragma unroll
        for (int off = 16; off > 0; off >>= 1)
            l += __shfl_xor_sync(0xffffffffu, l, off);
        const float inv = 1.f / l;

        // ---- write P (gmem coalesced + smem stage) ----
        const long arow = attn_head_base + (long)qr * 256;
#pragma unroll
        for (int jj = 0; jj < 8; jj++) {
            float p = e[jj] * inv;
            pr[jj * 32 + lane] = p;
            if (attn) attn[arow + jj * 32 + lane] = p;
        }
        __syncwarp();

        // ---- O row: lane owns dim d=lane; vectorized dot over j ----
        const float4* p4 = (const float4*)pr;
        const float4* v4 = (const float4*)(vst + lane * 268);
        float o = 0.f;
#pragma unroll 8
        for (int j4 = 0; j4 < 64; j4++) {
            float4 pv = p4[j4];
            float4 vv = v4[j4];
            o += pv.x * vv.x + pv.y * vv.y + pv.z * vv.z + pv.w * vv.w;
        }
        const int qy = qr >> 4, qx = qr & 15;
        const long gq = (long)b * 65536 + (long)(win_y * 16 + qy) * 256 + (win_x * 16 + qx);
        o_out[gq * CDIM + h * HDIM + lane] = o;
        __syncwarp();   // protect pr before next iteration overwrites
    }
}

// ---------------------------------------------------------------------------
extern "C" void kernel_launch(void* const* d_in, const int* in_sizes, int n_in,
                              void* d_out, int out_size)
{
    (void)in_sizes; (void)n_in;
    const float* x      = (const float*)d_in[0];
    const float* qkv_w  = (const float*)d_in[1];
    const float* qkv_b  = (const float*)d_in[2];
    const float* proj_w = (const float*)d_in[3];
    const float* proj_b = (const float*)d_in[4];

    float* qkv_buf = nullptr;
    float* o_buf   = nullptr;
    cudaGetSymbolAddress((void**)&qkv_buf, g_qkv);
    cudaGetSymbolAddress((void**)&o_buf,   g_o);

    float* out_ptr  = (float*)d_out;
    float* attn_ptr = nullptr;
    long osz = (long)out_size;
    if (osz >= OUT_ELEMS + ATTN_ELEMS) {
        out_ptr  = (float*)d_out;
        attn_ptr = (float*)d_out + OUT_ELEMS;
    } else if (osz == ATTN_ELEMS) {
        // attn-only output: write attn to d_out, proj result to scratch (qkv buf reused)
        attn_ptr = (float*)d_out;
        out_ptr  = qkv_buf;
    }

    // 1) QKV projection: [131072,256] @ [256,768] + bias
    sgemm_bias<<<dim3(QKVN / 128, (int)(MROWS / 128)), 256>>>(
        x, qkv_w, qkv_b, qkv_buf, QKVN, CDIM);

    // 2) Windowed attention (4096 = 512 windows * 8 heads)
    cudaFuncSetAttribute(attn_kernel, cudaFuncAttributeMaxDynamicSharedMemorySize, SM_BYTES);
    attn_kernel<<<NWIN * NHEAD, 256, SM_BYTES>>>(qkv_buf, o_buf, attn_ptr);

    // 3) Output projection: [131072,256] @ [256,256] + bias
    sgemm_bias<<<dim3(CDIM / 128, (int)(MROWS / 128)), 256>>>(
        o_buf, proj_w, proj_b, out_ptr, CDIM, CDIM);
}

// round 8
// speedup vs baseline: 1.5403x; 1.5403x over previous
#include <cuda_runtime.h>
#include <math.h>

// ---------------------------------------------------------------------------
// LocalSparseAttention (Swin-style windowed attention) — fp32x2 packed-FMA version
//   B=2, N=65536 (256x256), C=256, window=16 (256 tok/window), heads=8, hd=32
// ---------------------------------------------------------------------------

#define MROWS 131072L
#define CDIM  256
#define QKVN  768
#define NWIN  512
#define NHEAD 8
#define HDIM  32

static const long OUT_ELEMS  = MROWS * CDIM;                    // 33,554,432
static const long ATTN_ELEMS = (long)NWIN * NHEAD * 256 * 256;  // 268,435,456

__device__ float g_qkv[MROWS * QKVN];
__device__ float g_o  [MROWS * CDIM];

// ---- packed f32x2 helpers (sm_103a FFMA2 path; ptxas never auto-generates) ----
typedef unsigned long long u64;

__device__ __forceinline__ u64 pack2(float lo, float hi) {
    u64 r; asm("mov.b64 %0, {%1, %2};" : "=l"(r) : "f"(lo), "f"(hi)); return r;
}
__device__ __forceinline__ u64 dup2(float x) {
    u64 r; asm("mov.b64 %0, {%1, %1};" : "=l"(r) : "f"(x)); return r;
}
__device__ __forceinline__ void fma2(u64& d, u64 a, u64 b) {
    asm("fma.rn.f32x2 %0, %1, %2, %0;" : "+l"(d) : "l"(a), "l"(b));
}
__device__ __forceinline__ float hsum2(u64 v) {
    float a, b; asm("mov.b64 {%0, %1}, %2;" : "=f"(a), "=f"(b) : "l"(v)); return a + b;
}
__device__ __forceinline__ float2 unpk2(u64 v) {
    float2 r; asm("mov.b64 {%0, %1}, %2;" : "=f"(r.x), "=f"(r.y) : "l"(v)); return r;
}

// ---------------------------------------------------------------------------
// 128x128x8 fp32 register-tiled GEMM with bias, inner product via FFMA2.
// ---------------------------------------------------------------------------
__global__ __launch_bounds__(256, 2)
void sgemm_bias(const float* __restrict__ A, const float* __restrict__ B,
                const float* __restrict__ bias, float* __restrict__ C,
                int N, int K)
{
    __shared__ float As[8][132];
    __shared__ float Bs[8][128];

    const int tid = threadIdx.x;
    const int bm = blockIdx.y * 128;
    const int bn = blockIdx.x * 128;

    const int arow = tid >> 1;
    const int ac4  = (tid & 1) * 4;
    const int brow = tid >> 5;
    const int bc4  = (tid & 31) * 4;

    const float* Ag = A + (long)(bm + arow) * K + ac4;
    const float* Bg = B + (long)brow * N + bn + bc4;

    const int tr = (tid >> 4) * 4;
    const int tc = (tid & 15) * 4;

    u64 acc2[8][4];
#pragma unroll
    for (int i = 0; i < 8; i++)
#pragma unroll
        for (int j = 0; j < 4; j++) acc2[i][j] = 0ull;

    for (int kt = 0; kt < K; kt += 8) {
        float4 av = *(const float4*)(Ag + kt);
        float4 bv = *(const float4*)(Bg + (long)kt * N);
        As[ac4 + 0][arow] = av.x;
        As[ac4 + 1][arow] = av.y;
        As[ac4 + 2][arow] = av.z;
        As[ac4 + 3][arow] = av.w;
        *(float4*)(&Bs[brow][bc4]) = bv;
        __syncthreads();

#pragma unroll
        for (int kk = 0; kk < 8; kk++) {
            float a[8];
            *(float4*)(a)     = *(const float4*)(&As[kk][tr]);
            *(float4*)(a + 4) = *(const float4*)(&As[kk][tr + 64]);
            float4 q0 = *(const float4*)(&Bs[kk][tc]);
            float4 q1 = *(const float4*)(&Bs[kk][tc + 64]);
            u64 b2[4];
            b2[0] = pack2(q0.x, q0.y); b2[1] = pack2(q0.z, q0.w);
            b2[2] = pack2(q1.x, q1.y); b2[3] = pack2(q1.z, q1.w);
#pragma unroll
            for (int i = 0; i < 8; i++) {
                u64 ad = dup2(a[i]);
#pragma unroll
                for (int j = 0; j < 4; j++) fma2(acc2[i][j], ad, b2[j]);
            }
        }
        __syncthreads();
    }

    float bs0[4], bs1[4];
#pragma unroll
    for (int j = 0; j < 4; j++) {
        bs0[j] = bias[bn + tc + j];
        bs1[j] = bias[bn + 64 + tc + j];
    }
#pragma unroll
    for (int i = 0; i < 8; i++) {
        int row = bm + ((i < 4) ? (tr + i) : (64 + tr + i - 4));
        float* Crow = C + (long)row * N + bn;
        float2 c0 = unpk2(acc2[i][0]), c1 = unpk2(acc2[i][1]);
        float2 c2 = unpk2(acc2[i][2]), c3 = unpk2(acc2[i][3]);
        float4 o0, o1;
        o0.x = c0.x + bs0[0]; o0.y = c0.y + bs0[1];
        o0.z = c1.x + bs0[2]; o0.w = c1.y + bs0[3];
        o1.x = c2.x + bs1[0]; o1.y = c2.y + bs1[1];
        o1.z = c3.x + bs1[2]; o1.w = c3.y + bs1[3];
        *(float4*)(Crow + tc)      = o0;
        *(float4*)(Crow + 64 + tc) = o1;
    }
}

// ---------------------------------------------------------------------------
// Windowed attention: one block per (window, head). 8 warps, 4 query rows per
// warp iteration (K/V smem loads amortized 4x), FFMA2 dot products.
//   smem: K [256x36] + Vt [32x268] + P [8 warps x 4 rows x 256] + Qstage [8x128]
// ---------------------------------------------------------------------------
#define KS_OFF 0
#define VS_OFF 9216            // 256*36
#define PS_OFF 17792           // + 32*268
#define QS_OFF 25984           // + 8*1024
#define SM_FLOATS 27008        // + 8*128
#define SM_BYTES (SM_FLOATS * 4)

__global__ __launch_bounds__(256, 2)
void attn_kernel(const float* __restrict__ qkv, float* __restrict__ o_out,
                 float* __restrict__ attn)
{
    extern __shared__ float sm[];
    float* ks  = sm + KS_OFF;
    float* vst = sm + VS_OFF;
    float* ps  = sm + PS_OFF;
    float* qsm = sm + QS_OFF;

    const int bid = blockIdx.x;
    const int win = bid >> 3;
    const int h   = bid & 7;
    const int b     = win >> 8;
    const int win_y = (win >> 4) & 15;
    const int win_x = win & 15;

    const int tw = threadIdx.x;
    {   // K, V tile load (one token per thread)
        const int wy = tw >> 4, wx = tw & 15;
        const long g = (long)b * 65536 + (long)(win_y * 16 + wy) * 256 + (win_x * 16 + wx);
        const float4* src = (const float4*)(qkv + g * QKVN + h * HDIM);
#pragma unroll
        for (int d4 = 0; d4 < 8; d4++) {
            float4 kv = src[64 + d4];
            float4 vv = src[128 + d4];
            ((float4*)(ks + tw * 36))[d4] = kv;
            vst[(d4 * 4 + 0) * 268 + tw] = vv.x;
            vst[(d4 * 4 + 1) * 268 + tw] = vv.y;
            vst[(d4 * 4 + 2) * 268 + tw] = vv.z;
            vst[(d4 * 4 + 3) * 268 + tw] = vv.w;
        }
    }
    __syncthreads();

    const int lane = tw & 31;
    const int w    = tw >> 5;
    float* pw = ps  + w * 1024;
    float* qw = qsm + w * 128;
    const float scale = 0.17677669529663687f;   // 32^-0.5
    const long attn_base = ((long)win * NHEAD + h) * 65536;
    const long tok_base  = (long)b * 65536 + (long)(win_y * 16) * 256 + win_x * 16;

    // prefetch q for it=0 (lane covers (row = lane>>3, dims (lane&7)*4..+3))
    float4 qreg;
    {
        int row = w * 32 + (lane >> 3);
        long gq = tok_base + (long)(row >> 4) * 256 + (row & 15);
        qreg = *(const float4*)(qkv + gq * QKVN + h * HDIM + (lane & 7) * 4);
    }

    for (int it = 0; it < 8; it++) {
        const int rbase = w * 32 + it * 4;

        // stage q for the 4 rows of this iteration; prefetch next
        *(float4*)(qw + (lane >> 3) * 32 + (lane & 7) * 4) = qreg;
        __syncwarp();
        if (it < 7) {
            int row = w * 32 + (it + 1) * 4 + (lane >> 3);
            long gq = tok_base + (long)(row >> 4) * 256 + (row & 15);
            qreg = *(const float4*)(qkv + gq * QKVN + h * HDIM + (lane & 7) * 4);
        }

        // ---- QK^T for 4 rows: s2[r][jj] packs (even-d, odd-d) partial sums ----
        u64 s2[4][8];
#pragma unroll
        for (int r = 0; r < 4; r++)
#pragma unroll
            for (int jj = 0; jj < 8; jj++) s2[r][jj] = 0ull;

#pragma unroll
        for (int d4 = 0; d4 < 8; d4++) {
            u64 qa[4], qb[4];
#pragma unroll
            for (int r = 0; r < 4; r++) {
                float4 qv = *(const float4*)(qw + r * 32 + d4 * 4);  // broadcast
                qa[r] = pack2(qv.x, qv.y);
                qb[r] = pack2(qv.z, qv.w);
            }
#pragma unroll
            for (int jj = 0; jj < 8; jj++) {
                float4 kv = *(const float4*)(ks + (jj * 32 + lane) * 36 + d4 * 4);
                u64 ka = pack2(kv.x, kv.y);
                u64 kb = pack2(kv.z, kv.w);
#pragma unroll
                for (int r = 0; r < 4; r++) {
                    fma2(s2[r][jj], qa[r], ka);
                    fma2(s2[r][jj], qb[r], kb);
                }
            }
        }

        // ---- softmax per row + write P (smem stage + streaming gmem) ----
#pragma unroll
        for (int r = 0; r < 4; r++) {
            float sv[8];
#pragma unroll
            for (int jj = 0; jj < 8; jj++) sv[jj] = hsum2(s2[r][jj]) * scale;
            float m = sv[0];
#pragma unroll
            for (int jj = 1; jj < 8; jj++) m = fmaxf(m, sv[jj]);
#pragma unroll
            for (int off = 16; off > 0; off >>= 1)
                m = fmaxf(m, __shfl_xor_sync(0xffffffffu, m, off));
            float l = 0.f;
#pragma unroll
            for (int jj = 0; jj < 8; jj++) { sv[jj] = __expf(sv[jj] - m); l += sv[jj]; }
#pragma unroll
            for (int off = 16; off > 0; off >>= 1)
                l += __shfl_xor_sync(0xffffffffu, l, off);
            const float inv = 1.f / l;
            const long arow = attn_base + (long)(rbase + r) * 256;
#pragma unroll
            for (int jj = 0; jj < 8; jj++) {
                float p = sv[jj] * inv;
                pw[r * 256 + jj * 32 + lane] = p;
                if (attn) __stcs(attn + arow + jj * 32 + lane, p);
            }
        }
        __syncwarp();

        // ---- P @ V for 4 rows: lane owns output dim d=lane ----
        u64 o2[4];
#pragma unroll
        for (int r = 0; r < 4; r++) o2[r] = 0ull;
        const float4* v4 = (const float4*)(vst + lane * 268);
        const u64*   p2 = (const u64*)pw;
#pragma unroll 8
        for (int j4 = 0; j4 < 64; j4++) {
            float4 vv = v4[j4];
            u64 va = pack2(vv.x, vv.y);
            u64 vb = pack2(vv.z, vv.w);
#pragma unroll
            for (int r = 0; r < 4; r++) {
                u64 pa = p2[r * 128 + j4 * 2];      // 8B broadcast
                u64 pb = p2[r * 128 + j4 * 2 + 1];
                fma2(o2[r], pa, va);
                fma2(o2[r], pb, vb);
            }
        }
#pragma unroll
        for (int r = 0; r < 4; r++) {
            int row = rbase + r;
            long gq = tok_base + (long)(row >> 4) * 256 + (row & 15);
            o_out[gq * CDIM + h * HDIM + lane] = hsum2(o2[r]);
        }
        __syncwarp();   // protect pw / qw before next iteration overwrites
    }
}

// ---------------------------------------------------------------------------
extern "C" void kernel_launch(void* const* d_in, const int* in_sizes, int n_in,
                              void* d_out, int out_size)
{
    (void)in_sizes; (void)n_in;
    const float* x      = (const float*)d_in[0];
    const float* qkv_w  = (const float*)d_in[1];
    const float* qkv_b  = (const float*)d_in[2];
    const float* proj_w = (const float*)d_in[3];
    const float* proj_b = (const float*)d_in[4];

    float* qkv_buf = nullptr;
    float* o_buf   = nullptr;
    cudaGetSymbolAddress((void**)&qkv_buf, g_qkv);
    cudaGetSymbolAddress((void**)&o_buf,   g_o);

    float* out_ptr  = (float*)d_out;
    float* attn_ptr = nullptr;
    long osz = (long)out_size;
    if (osz >= OUT_ELEMS + ATTN_ELEMS) {
        out_ptr  = (float*)d_out;
        attn_ptr = (float*)d_out + OUT_ELEMS;
    } else if (osz == ATTN_ELEMS) {
        attn_ptr = (float*)d_out;
        out_ptr  = qkv_buf;
    }

    // 1) QKV projection: [131072,256] @ [256,768] + bias
    sgemm_bias<<<dim3(QKVN / 128, (int)(MROWS / 128)), 256>>>(
        x, qkv_w, qkv_b, qkv_buf, QKVN, CDIM);

    // 2) Windowed attention (512 windows * 8 heads)
    cudaFuncSetAttribute(attn_kernel, cudaFuncAttributeMaxDynamicSharedMemorySize, SM_BYTES);
    attn_kernel<<<NWIN * NHEAD, 256, SM_BYTES>>>(qkv_buf, o_buf, attn_ptr);

    // 3) Output projection: [131072,256] @ [256,256] + bias
    sgemm_bias<<<dim3(CDIM / 128, (int)(MROWS / 128)), 256>>>(
        o_buf, proj_w, proj_b, out_ptr, CDIM, CDIM);
}

// round 9
// speedup vs baseline: 1.8937x; 1.2294x over previous
#include <cuda_runtime.h>
#include <math.h>
#include <stdint.h>

// ---------------------------------------------------------------------------
// LocalSparseAttention — tf32 tensor-core GEMMs + fp32x2 attention
//   B=2, N=65536 (256x256), C=256, window=16 (256 tok/window), heads=8, hd=32
// ---------------------------------------------------------------------------

#define MROWS 131072L
#define CDIM  256
#define QKVN  768
#define NWIN  512
#define NHEAD 8
#define HDIM  32

static const long OUT_ELEMS  = MROWS * CDIM;                    // 33,554,432
static const long ATTN_ELEMS = (long)NWIN * NHEAD * 256 * 256;  // 268,435,456

__device__ float g_qkv[MROWS * QKVN];   // qkv projection output (fp32)
__device__ float g_o  [MROWS * CDIM];   // attention output (tf32-rounded fp32)
__device__ float g_xt [MROWS * CDIM];   // x rounded to tf32
__device__ float g_wq [CDIM * QKVN];    // qkv_w rounded to tf32
__device__ float g_wp [CDIM * CDIM];    // proj_w rounded to tf32

// ---- packed f32x2 helpers (attention path) ----
typedef unsigned long long u64;
__device__ __forceinline__ u64 pack2(float lo, float hi) {
    u64 r; asm("mov.b64 %0, {%1, %2};" : "=l"(r) : "f"(lo), "f"(hi)); return r;
}
__device__ __forceinline__ void fma2(u64& d, u64 a, u64 b) {
    asm("fma.rn.f32x2 %0, %1, %2, %0;" : "+l"(d) : "l"(a), "l"(b));
}
__device__ __forceinline__ float hsum2(u64 v) {
    float a, b; asm("mov.b64 {%0, %1}, %2;" : "=f"(a), "=f"(b) : "l"(v)); return a + b;
}

// ---- tf32 helpers ----
__device__ __forceinline__ float cvt_tf32(float x) {
    uint32_t r; asm("cvt.rna.tf32.f32 %0, %1;" : "=r"(r) : "f"(x));
    return __uint_as_float(r);
}
__device__ __forceinline__ void cp_async16(uint32_t dst, const void* src) {
    asm volatile("cp.async.cg.shared.global [%0], [%1], 16;" :: "r"(dst), "l"(src));
}
__device__ __forceinline__ void mma_tf32(float* d, const uint32_t* a,
                                         uint32_t b0, uint32_t b1) {
    asm volatile(
        "mma.sync.aligned.m16n8k8.row.col.f32.tf32.tf32.f32 "
        "{%0,%1,%2,%3}, {%4,%5,%6,%7}, {%8,%9}, {%0,%1,%2,%3};"
        : "+f"(d[0]), "+f"(d[1]), "+f"(d[2]), "+f"(d[3])
        : "r"(a[0]), "r"(a[1]), "r"(a[2]), "r"(a[3]), "r"(b0), "r"(b1));
}

// ---------------------------------------------------------------------------
// Elementwise round-to-nearest tf32 (zero-mean rounding; avoids mma's RZ bias)
// ---------------------------------------------------------------------------
__global__ void cvt_tf32_kernel(const float* __restrict__ in,
                                float* __restrict__ out, long n4)
{
    long i = (long)blockIdx.x * blockDim.x + threadIdx.x;
    long stride = (long)gridDim.x * blockDim.x;
    for (; i < n4; i += stride) {
        float4 v = ((const float4*)in)[i];
        v.x = cvt_tf32(v.x); v.y = cvt_tf32(v.y);
        v.z = cvt_tf32(v.z); v.w = cvt_tf32(v.w);
        ((float4*)out)[i] = v;
    }
}

// ---------------------------------------------------------------------------
// tf32 tensor-core GEMM: C[M,N] = A[M,256] @ B[256,N] + bias
//   Block 128x128, K-tile 32, 8 warps (4M x 2N), warp tile 32x64.
//   cp.async double-buffered. A,B pre-rounded to tf32.
// ---------------------------------------------------------------------------
#define SA 36     // As row stride (bank = 4m+k, conflict-free frag loads)
#define SB 132    // Bs row stride (conflict-free cp.async stores)
#define GEMM_SMEM ((2*128*SA + 2*32*SB) * 4)   // 70,656 bytes

__global__ __launch_bounds__(256, 2)
void sgemm_tf32(const float* __restrict__ A, const float* __restrict__ B,
                const float* __restrict__ bias, float* __restrict__ C, int N)
{
    extern __shared__ float smem[];
    float* As = smem;                 // [2][128*SA]
    float* Bs = smem + 2 * 128 * SA;  // [2][32*SB]

    const int tid  = threadIdx.x;
    const int bm   = blockIdx.y * 128;
    const int bn   = blockIdx.x * 128;
    const int lane = tid & 31;
    const int warp = tid >> 5;
    const int warpM = warp >> 1;      // 0..3
    const int warpN = warp & 1;       // 0..1

    // loader mapping
    const int am  = tid >> 1;          // 0..127 (A row)
    const int ak  = (tid & 1) * 16;    // A k-offset 0/16
    const int bk  = tid & 31;          // B k-row 0..31
    const int bn0 = (tid >> 5) * 16;   // B n-offset

    const float* Ag = A + (long)(bm + am) * 256 + ak;
    const float* Bg = B + (long)bk * N + bn + bn0;

    const uint32_t as_base = (uint32_t)__cvta_generic_to_shared(As);
    const uint32_t bs_base = (uint32_t)__cvta_generic_to_shared(Bs);

    float d[2][8][4];
#pragma unroll
    for (int mm = 0; mm < 2; mm++)
#pragma unroll
        for (int nm = 0; nm < 8; nm++)
#pragma unroll
            for (int q = 0; q < 4; q++) d[mm][nm][q] = 0.f;

#define ISSUE(kt) do {                                                         \
        int buf_ = (kt) & 1;                                                   \
        uint32_t ad_ = as_base + (uint32_t)(buf_ * 128 * SA + am * SA + ak) * 4; \
        const float* asrc_ = Ag + (kt) * 32;                                   \
        _Pragma("unroll")                                                      \
        for (int q = 0; q < 4; q++) cp_async16(ad_ + q * 16, asrc_ + q * 4);   \
        uint32_t bd_ = bs_base + (uint32_t)(buf_ * 32 * SB + bk * SB + bn0) * 4; \
        const float* bsrc_ = Bg + (long)(kt) * 32 * N;                         \
        _Pragma("unroll")                                                      \
        for (int q = 0; q < 4; q++) cp_async16(bd_ + q * 16, bsrc_ + q * 4);   \
        asm volatile("cp.async.commit_group;");                                \
    } while (0)

    ISSUE(0);
    ISSUE(1);

    for (int kt = 0; kt < 8; kt++) {
        if (kt < 6) asm volatile("cp.async.wait_group 1;");
        else        asm volatile("cp.async.wait_group 0;");
        __syncthreads();

        const float* Ab = As + (kt & 1) * 128 * SA;
        const float* Bb = Bs + (kt & 1) * 32 * SB;

#pragma unroll
        for (int ks = 0; ks < 4; ks++) {
            const int k = ks * 8;
            uint32_t a[2][4];
#pragma unroll
            for (int mm = 0; mm < 2; mm++) {
                const int m = warpM * 32 + mm * 16 + (lane >> 2);
                const float* p = Ab + m * SA + k + (lane & 3);
                a[mm][0] = __float_as_uint(p[0]);
                a[mm][1] = __float_as_uint(p[8 * SA]);
                a[mm][2] = __float_as_uint(p[4]);
                a[mm][3] = __float_as_uint(p[8 * SA + 4]);
            }
#pragma unroll
            for (int nm = 0; nm < 8; nm++) {
                const int n = warpN * 64 + nm * 8 + (lane >> 2);
                const float* p = Bb + (k + (lane & 3)) * SB + n;
                uint32_t b0 = __float_as_uint(p[0]);
                uint32_t b1 = __float_as_uint(p[4 * SB]);
#pragma unroll
                for (int mm = 0; mm < 2; mm++)
                    mma_tf32(d[mm][nm], a[mm], b0, b1);
            }
        }
        __syncthreads();
        if (kt + 2 < 8) ISSUE(kt + 2);
    }
#undef ISSUE

    // epilogue: bias + store (float2 per fragment half)
#pragma unroll
    for (int nm = 0; nm < 8; nm++) {
        const int col = bn + warpN * 64 + nm * 8 + (lane & 3) * 2;
        const float2 bv = *(const float2*)(bias + col);
#pragma unroll
        for (int mm = 0; mm < 2; mm++) {
            const int r0 = bm + warpM * 32 + mm * 16 + (lane >> 2);
            float2 v0 = { d[mm][nm][0] + bv.x, d[mm][nm][1] + bv.y };
            float2 v1 = { d[mm][nm][2] + bv.x, d[mm][nm][3] + bv.y };
            *(float2*)(C + (long)r0 * N + col)       = v0;
            *(float2*)(C + (long)(r0 + 8) * N + col) = v1;
        }
    }
}

// ---------------------------------------------------------------------------
// Windowed attention (unchanged from R8 except: o stored tf32-rounded so the
// proj GEMM consumes pre-rounded input with no extra pass).
// ---------------------------------------------------------------------------
#define KS_OFF 0
#define VS_OFF 9216            // 256*36
#define PS_OFF 17792           // + 32*268
#define QS_OFF 25984           // + 8*1024
#define SM_FLOATS 27008        // + 8*128
#define SM_BYTES (SM_FLOATS * 4)

__global__ __launch_bounds__(256, 2)
void attn_kernel(const float* __restrict__ qkv, float* __restrict__ o_out,
                 float* __restrict__ attn)
{
    extern __shared__ float sm[];
    float* ks  = sm + KS_OFF;
    float* vst = sm + VS_OFF;
    float* ps  = sm + PS_OFF;
    float* qsm = sm + QS_OFF;

    const int bid = blockIdx.x;
    const int win = bid >> 3;
    const int h   = bid & 7;
    const int b     = win >> 8;
    const int win_y = (win >> 4) & 15;
    const int win_x = win & 15;

    const int tw = threadIdx.x;
    {   // K, V tile load (one token per thread)
        const int wy = tw >> 4, wx = tw & 15;
        const long g = (long)b * 65536 + (long)(win_y * 16 + wy) * 256 + (win_x * 16 + wx);
        const float4* src = (const float4*)(qkv + g * QKVN + h * HDIM);
#pragma unroll
        for (int d4 = 0; d4 < 8; d4++) {
            float4 kv = src[64 + d4];
            float4 vv = src[128 + d4];
            ((float4*)(ks + tw * 36))[d4] = kv;
            vst[(d4 * 4 + 0) * 268 + tw] = vv.x;
            vst[(d4 * 4 + 1) * 268 + tw] = vv.y;
            vst[(d4 * 4 + 2) * 268 + tw] = vv.z;
            vst[(d4 * 4 + 3) * 268 + tw] = vv.w;
        }
    }
    __syncthreads();

    const int lane = tw & 31;
    const int w    = tw >> 5;
    float* pw = ps  + w * 1024;
    float* qw = qsm + w * 128;
    const float scale = 0.17677669529663687f;   // 32^-0.5
    const long attn_base = ((long)win * NHEAD + h) * 65536;
    const long tok_base  = (long)b * 65536 + (long)(win_y * 16) * 256 + win_x * 16;

    float4 qreg;
    {
        int row = w * 32 + (lane >> 3);
        long gq = tok_base + (long)(row >> 4) * 256 + (row & 15);
        qreg = *(const float4*)(qkv + gq * QKVN + h * HDIM + (lane & 7) * 4);
    }

    for (int it = 0; it < 8; it++) {
        const int rbase = w * 32 + it * 4;

        *(float4*)(qw + (lane >> 3) * 32 + (lane & 7) * 4) = qreg;
        __syncwarp();
        if (it < 7) {
            int row = w * 32 + (it + 1) * 4 + (lane >> 3);
            long gq = tok_base + (long)(row >> 4) * 256 + (row & 15);
            qreg = *(const float4*)(qkv + gq * QKVN + h * HDIM + (lane & 7) * 4);
        }

        // ---- QK^T for 4 rows ----
        u64 s2[4][8];
#pragma unroll
        for (int r = 0; r < 4; r++)
#pragma unroll
            for (int jj = 0; jj < 8; jj++) s2[r][jj] = 0ull;

#pragma unroll
        for (int d4 = 0; d4 < 8; d4++) {
            u64 qa[4], qb[4];
#pragma unroll
            for (int r = 0; r < 4; r++) {
                float4 qv = *(const float4*)(qw + r * 32 + d4 * 4);
                qa[r] = pack2(qv.x, qv.y);
                qb[r] = pack2(qv.z, qv.w);
            }
#pragma unroll
            for (int jj = 0; jj < 8; jj++) {
                float4 kv = *(const float4*)(ks + (jj * 32 + lane) * 36 + d4 * 4);
                u64 ka = pack2(kv.x, kv.y);
                u64 kb = pack2(kv.z, kv.w);
#pragma unroll
                for (int r = 0; r < 4; r++) {
                    fma2(s2[r][jj], qa[r], ka);
                    fma2(s2[r][jj], qb[r], kb);
                }
            }
        }

        // ---- softmax + write P ----
#pragma unroll
        for (int r = 0; r < 4; r++) {
            float sv[8];
#pragma unroll
            for (int jj = 0; jj < 8; jj++) sv[jj] = hsum2(s2[r][jj]) * scale;
            float m = sv[0];
#pragma unroll
            for (int jj = 1; jj < 8; jj++) m = fmaxf(m, sv[jj]);
#pragma unroll
            for (int off = 16; off > 0; off >>= 1)
                m = fmaxf(m, __shfl_xor_sync(0xffffffffu, m, off));
            float l = 0.f;
#pragma unroll
            for (int jj = 0; jj < 8; jj++) { sv[jj] = __expf(sv[jj] - m); l += sv[jj]; }
#pragma unroll
            for (int off = 16; off > 0; off >>= 1)
                l += __shfl_xor_sync(0xffffffffu, l, off);
            const float inv = 1.f / l;
            const long arow = attn_base + (long)(rbase + r) * 256;
#pragma unroll
            for (int jj = 0; jj < 8; jj++) {
                float p = sv[jj] * inv;
                pw[r * 256 + jj * 32 + lane] = p;
                if (attn) __stcs(attn + arow + jj * 32 + lane, p);
            }
        }
        __syncwarp();

        // ---- P @ V ----
        u64 o2[4];
#pragma unroll
        for (int r = 0; r < 4; r++) o2[r] = 0ull;
        const float4* v4 = (const float4*)(vst + lane * 268);
        const u64*   p2 = (const u64*)pw;
#pragma unroll 8
        for (int j4 = 0; j4 < 64; j4++) {
            float4 vv = v4[j4];
            u64 va = pack2(vv.x, vv.y);
            u64 vb = pack2(vv.z, vv.w);
#pragma unroll
            for (int r = 0; r < 4; r++) {
                u64 pa = p2[r * 128 + j4 * 2];
                u64 pb = p2[r * 128 + j4 * 2 + 1];
                fma2(o2[r], pa, va);
                fma2(o2[r], pb, vb);
            }
        }
#pragma unroll
        for (int r = 0; r < 4; r++) {
            int row = rbase + r;
            long gq = tok_base + (long)(row >> 4) * 256 + (row & 15);
            // round to tf32 here: proj GEMM consumes pre-rounded input for free
            o_out[gq * CDIM + h * HDIM + lane] = cvt_tf32(hsum2(o2[r]));
        }
        __syncwarp();
    }
}

// ---------------------------------------------------------------------------
extern "C" void kernel_launch(void* const* d_in, const int* in_sizes, int n_in,
                              void* d_out, int out_size)
{
    (void)in_sizes; (void)n_in;
    const float* x      = (const float*)d_in[0];
    const float* qkv_w  = (const float*)d_in[1];
    const float* qkv_b  = (const float*)d_in[2];
    const float* proj_w = (const float*)d_in[3];
    const float* proj_b = (const float*)d_in[4];

    float *qkv_buf, *o_buf, *xt, *wq, *wp;
    cudaGetSymbolAddress((void**)&qkv_buf, g_qkv);
    cudaGetSymbolAddress((void**)&o_buf,   g_o);
    cudaGetSymbolAddress((void**)&xt,      g_xt);
    cudaGetSymbolAddress((void**)&wq,      g_wq);
    cudaGetSymbolAddress((void**)&wp,      g_wp);

    float* out_ptr  = (float*)d_out;
    float* attn_ptr = nullptr;
    long osz = (long)out_size;
    if (osz >= OUT_ELEMS + ATTN_ELEMS) {
        out_ptr  = (float*)d_out;
        attn_ptr = (float*)d_out + OUT_ELEMS;
    } else if (osz == ATTN_ELEMS) {
        attn_ptr = (float*)d_out;
        out_ptr  = qkv_buf;
    }

    // 0) Round inputs/weights to tf32 (rna — zero-mean rounding)
    cvt_tf32_kernel<<<4096, 256>>>(x,      xt, OUT_ELEMS / 4);
    cvt_tf32_kernel<<<192,  256>>>(qkv_w,  wq, (long)(CDIM * QKVN) / 4);
    cvt_tf32_kernel<<<64,   256>>>(proj_w, wp, (long)(CDIM * CDIM) / 4);

    // 1) QKV projection: [131072,256] @ [256,768] + bias (tf32 tensor cores)
    cudaFuncSetAttribute(sgemm_tf32, cudaFuncAttributeMaxDynamicSharedMemorySize, GEMM_SMEM);
    sgemm_tf32<<<dim3(QKVN / 128, (int)(MROWS / 128)), 256, GEMM_SMEM>>>(
        xt, wq, qkv_b, qkv_buf, QKVN);

    // 2) Windowed attention (512 windows * 8 heads), fp32; o stored tf32-rounded
    cudaFuncSetAttribute(attn_kernel, cudaFuncAttributeMaxDynamicSharedMemorySize, SM_BYTES);
    attn_kernel<<<NWIN * NHEAD, 256, SM_BYTES>>>(qkv_buf, o_buf, attn_ptr);

    // 3) Output projection: [131072,256] @ [256,256] + bias (tf32 tensor cores)
    sgemm_tf32<<<dim3(CDIM / 128, (int)(MROWS / 128)), 256, GEMM_SMEM>>>(
        o_buf, wp, proj_b, out_ptr, CDIM);
}

// round 13
// speedup vs baseline: 2.4074x; 1.2713x over previous
#include <cuda_runtime.h>
#include <math.h>
#include <stdint.h>

// ---------------------------------------------------------------------------
// LocalSparseAttention — tf32 mma.sync GEMMs + tf32 mma.sync attention
//   B=2, N=65536 (256x256), C=256, window=16 (256 tok/window), heads=8, hd=32
// ---------------------------------------------------------------------------

#define MROWS 131072L
#define CDIM  256
#define QKVN  768
#define NWIN  512
#define NHEAD 8
#define HDIM  32

static const long OUT_ELEMS  = MROWS * CDIM;                    // 33,554,432
static const long ATTN_ELEMS = (long)NWIN * NHEAD * 256 * 256;  // 268,435,456

__device__ float g_qkv[MROWS * QKVN];   // qkv projection output (fp32)
__device__ float g_o  [MROWS * CDIM];   // attention output (tf32-rounded fp32)
__device__ float g_xt [MROWS * CDIM];   // x rounded to tf32
__device__ float g_wq [CDIM * QKVN];    // qkv_w rounded to tf32
__device__ float g_wp [CDIM * CDIM];    // proj_w rounded to tf32

// ---- tf32 / async helpers ----
__device__ __forceinline__ float cvt_tf32(float x) {
    uint32_t r; asm("cvt.rna.tf32.f32 %0, %1;" : "=r"(r) : "f"(x));
    return __uint_as_float(r);
}
__device__ __forceinline__ void cp_async16(uint32_t dst, const void* src) {
    asm volatile("cp.async.cg.shared.global [%0], [%1], 16;" :: "r"(dst), "l"(src));
}
__device__ __forceinline__ void mma_tf32(float* d, const uint32_t* a,
                                         uint32_t b0, uint32_t b1) {
    asm volatile(
        "mma.sync.aligned.m16n8k8.row.col.f32.tf32.tf32.f32 "
        "{%0,%1,%2,%3}, {%4,%5,%6,%7}, {%8,%9}, {%0,%1,%2,%3};"
        : "+f"(d[0]), "+f"(d[1]), "+f"(d[2]), "+f"(d[3])
        : "r"(a[0]), "r"(a[1]), "r"(a[2]), "r"(a[3]), "r"(b0), "r"(b1));
}

// ---------------------------------------------------------------------------
// Elementwise round-to-nearest tf32
// ---------------------------------------------------------------------------
__global__ void cvt_tf32_kernel(const float* __restrict__ in,
                                float* __restrict__ out, long n4)
{
    long i = (long)blockIdx.x * blockDim.x + threadIdx.x;
    long stride = (long)gridDim.x * blockDim.x;
    for (; i < n4; i += stride) {
        float4 v = ((const float4*)in)[i];
        v.x = cvt_tf32(v.x); v.y = cvt_tf32(v.y);
        v.z = cvt_tf32(v.z); v.w = cvt_tf32(v.w);
        ((float4*)out)[i] = v;
    }
}

// ---------------------------------------------------------------------------
// tf32 tensor-core GEMM (unchanged from R9 — measured 595us QKV)
// ---------------------------------------------------------------------------
#define SA 36
#define SB 132
#define GEMM_SMEM ((2*128*SA + 2*32*SB) * 4)   // 70,656 bytes

__global__ __launch_bounds__(256, 2)
void sgemm_tf32(const float* __restrict__ A, const float* __restrict__ B,
                const float* __restrict__ bias, float* __restrict__ C, int N)
{
    extern __shared__ float smem[];
    float* As = smem;
    float* Bs = smem + 2 * 128 * SA;

    const int tid  = threadIdx.x;
    const int bm   = blockIdx.y * 128;
    const int bn   = blockIdx.x * 128;
    const int lane = tid & 31;
    const int warp = tid >> 5;
    const int warpM = warp >> 1;
    const int warpN = warp & 1;

    const int am  = tid >> 1;
    const int ak  = (tid & 1) * 16;
    const int bk  = tid & 31;
    const int bn0 = (tid >> 5) * 16;

    const float* Ag = A + (long)(bm + am) * 256 + ak;
    const float* Bg = B + (long)bk * N + bn + bn0;

    const uint32_t as_base = (uint32_t)__cvta_generic_to_shared(As);
    const uint32_t bs_base = (uint32_t)__cvta_generic_to_shared(Bs);

    float d[2][8][4];
#pragma unroll
    for (int mm = 0; mm < 2; mm++)
#pragma unroll
        for (int nm = 0; nm < 8; nm++)
#pragma unroll
            for (int q = 0; q < 4; q++) d[mm][nm][q] = 0.f;

#define ISSUE(kt) do {                                                         \
        int buf_ = (kt) & 1;                                                   \
        uint32_t ad_ = as_base + (uint32_t)(buf_ * 128 * SA + am * SA + ak) * 4; \
        const float* asrc_ = Ag + (kt) * 32;                                   \
        _Pragma("unroll")                                                      \
        for (int q = 0; q < 4; q++) cp_async16(ad_ + q * 16, asrc_ + q * 4);   \
        uint32_t bd_ = bs_base + (uint32_t)(buf_ * 32 * SB + bk * SB + bn0) * 4; \
        const float* bsrc_ = Bg + (long)(kt) * 32 * N;                         \
        _Pragma("unroll")                                                      \
        for (int q = 0; q < 4; q++) cp_async16(bd_ + q * 16, bsrc_ + q * 4);   \
        asm volatile("cp.async.commit_group;");                                \
    } while (0)

    ISSUE(0);
    ISSUE(1);

    for (int kt = 0; kt < 8; kt++) {
        if (kt < 6) asm volatile("cp.async.wait_group 1;");
        else        asm volatile("cp.async.wait_group 0;");
        __syncthreads();

        const float* Ab = As + (kt & 1) * 128 * SA;
        const float* Bb = Bs + (kt & 1) * 32 * SB;

#pragma unroll
        for (int ks = 0; ks < 4; ks++) {
            const int k = ks * 8;
            uint32_t a[2][4];
#pragma unroll
            for (int mm = 0; mm < 2; mm++) {
                const int m = warpM * 32 + mm * 16 + (lane >> 2);
                const float* p = Ab + m * SA + k + (lane & 3);
                a[mm][0] = __float_as_uint(p[0]);
                a[mm][1] = __float_as_uint(p[8 * SA]);
                a[mm][2] = __float_as_uint(p[4]);
                a[mm][3] = __float_as_uint(p[8 * SA + 4]);
            }
#pragma unroll
            for (int nm = 0; nm < 8; nm++) {
                const int n = warpN * 64 + nm * 8 + (lane >> 2);
                const float* p = Bb + (k + (lane & 3)) * SB + n;
                uint32_t b0 = __float_as_uint(p[0]);
                uint32_t b1 = __float_as_uint(p[4 * SB]);
#pragma unroll
                for (int mm = 0; mm < 2; mm++)
                    mma_tf32(d[mm][nm], a[mm], b0, b1);
            }
        }
        __syncthreads();
        if (kt + 2 < 8) ISSUE(kt + 2);
    }
#undef ISSUE

#pragma unroll
    for (int nm = 0; nm < 8; nm++) {
        const int col = bn + warpN * 64 + nm * 8 + (lane & 3) * 2;
        const float2 bv = *(const float2*)(bias + col);
#pragma unroll
        for (int mm = 0; mm < 2; mm++) {
            const int r0 = bm + warpM * 32 + mm * 16 + (lane >> 2);
            float2 v0 = { d[mm][nm][0] + bv.x, d[mm][nm][1] + bv.y };
            float2 v1 = { d[mm][nm][2] + bv.x, d[mm][nm][3] + bv.y };
            *(float2*)(C + (long)r0 * N + col)       = v0;
            *(float2*)(C + (long)(r0 + 8) * N + col) = v1;
        }
    }
}

// ---------------------------------------------------------------------------
// Windowed attention on tensor cores. One block per (window, head), 256 thr.
//   KT [32][264]  K dim-major tf32   (B-frag for S = Q@K^T)
//   VS [256][40]  V row-major tf32   (B-frag for O = P@V)
//   SS [32][264]  S scores -> P (in place) -> PV partials [8][32][33]
//   QS [32][36]   Q chunk tf32
//   8 chunks of 32 query rows; warps: S cols / softmax rows / PV K-slices.
// ---------------------------------------------------------------------------
#define AT_KT 0
#define AT_VS 8448               // 32*264
#define AT_SS 18688              // + 256*40
#define AT_QS 27136              // + 32*264
#define AT_FLOATS 28288          // + 32*36
#define AT_BYTES (AT_FLOATS * 4) // 113,152

__global__ __launch_bounds__(256, 2)
void attn_tc(const float* __restrict__ qkv, float* __restrict__ o_out,
             float* __restrict__ attn)
{
    extern __shared__ float sm[];
    float* KT = sm + AT_KT;
    float* VS = sm + AT_VS;
    float* SS = sm + AT_SS;
    float* QS = sm + AT_QS;

    const int bid = blockIdx.x;
    const int win = bid >> 3, h = bid & 7;
    const int b = win >> 8, win_y = (win >> 4) & 15, win_x = win & 15;
    const int tid  = threadIdx.x;
    const int lane = tid & 31, w = tid >> 5;
    const int g = lane >> 2, c = lane & 3;

    const long tok_base  = (long)b * 65536 + (long)(win_y * 16) * 256 + win_x * 16;
    const long attn_base = ((long)win * NHEAD + h) * 65536;
    const float scale = 0.17677669529663687f;   // 32^-0.5

    // ---- init: K transposed + V row-major, both tf32-rounded ----
    {
        const int t = tid;
        const long gtok = tok_base + (long)(t >> 4) * 256 + (t & 15);
        const float4* src = (const float4*)(qkv + gtok * QKVN + h * HDIM);
#pragma unroll
        for (int d4 = 0; d4 < 8; d4++) {
            float4 kv = src[64 + d4];
            float4 vv = src[128 + d4];
            KT[(d4 * 4 + 0) * 264 + t] = cvt_tf32(kv.x);
            KT[(d4 * 4 + 1) * 264 + t] = cvt_tf32(kv.y);
            KT[(d4 * 4 + 2) * 264 + t] = cvt_tf32(kv.z);
            KT[(d4 * 4 + 3) * 264 + t] = cvt_tf32(kv.w);
            vv.x = cvt_tf32(vv.x); vv.y = cvt_tf32(vv.y);
            vv.z = cvt_tf32(vv.z); vv.w = cvt_tf32(vv.w);
            *(float4*)(VS + t * 40 + d4 * 4) = vv;
        }
    }

    for (int qc = 0; qc < 8; qc++) {
        // ---- load Q chunk (rows qc*32..+31), tf32-rounded ----
        {
            const int row = tid >> 3;
            const int dc  = (tid & 7) * 4;
            const int rw  = qc * 32 + row;
            const long gtok = tok_base + (long)(rw >> 4) * 256 + (rw & 15);
            float4 qv = *(const float4*)(qkv + gtok * QKVN + h * HDIM + dc);
            qv.x = cvt_tf32(qv.x); qv.y = cvt_tf32(qv.y);
            qv.z = cvt_tf32(qv.z); qv.w = cvt_tf32(qv.w);
            *(float4*)(QS + row * 36 + dc) = qv;
        }
        __syncthreads();                               // (1) Q/K/V ready

        // ---- S = Qc @ K^T : warp w owns cols [w*32, w*32+32) ----
        float d[2][4][4];
#pragma unroll
        for (int mm = 0; mm < 2; mm++)
#pragma unroll
            for (int nm = 0; nm < 4; nm++)
#pragma unroll
                for (int q = 0; q < 4; q++) d[mm][nm][q] = 0.f;

#pragma unroll
        for (int ks = 0; ks < 4; ks++) {
            const int kof = ks * 8;
            uint32_t a[2][4];
#pragma unroll
            for (int mm = 0; mm < 2; mm++) {
                const float* p = QS + (mm * 16 + g) * 36 + kof + c;
                a[mm][0] = __float_as_uint(p[0]);
                a[mm][1] = __float_as_uint(p[8 * 36]);
                a[mm][2] = __float_as_uint(p[4]);
                a[mm][3] = __float_as_uint(p[8 * 36 + 4]);
            }
#pragma unroll
            for (int nm = 0; nm < 4; nm++) {
                const float* p = KT + (kof + c) * 264 + w * 32 + nm * 8 + g;
                uint32_t b0 = __float_as_uint(p[0]);
                uint32_t b1 = __float_as_uint(p[4 * 264]);
                mma_tf32(d[0][nm], a[0], b0, b1);
                mma_tf32(d[1][nm], a[1], b0, b1);
            }
        }
        // stage S to smem (row stride 264: all float2 offsets even -> aligned)
#pragma unroll
        for (int mm = 0; mm < 2; mm++)
#pragma unroll
            for (int nm = 0; nm < 4; nm++) {
                float* p = SS + (mm * 16 + g) * 264 + w * 32 + nm * 8 + 2 * c;
                *(float2*)p             = make_float2(d[mm][nm][0], d[mm][nm][1]);
                *(float2*)(p + 8 * 264) = make_float2(d[mm][nm][2], d[mm][nm][3]);
            }
        __syncthreads();                               // (2) S complete

        // ---- softmax: warp w owns rows w*4..w*4+3; write attn + P(tf32) ----
#pragma unroll
        for (int i = 0; i < 4; i++) {
            const int row = w * 4 + i;
            float sv[8];
#pragma unroll
            for (int jj = 0; jj < 8; jj++)
                sv[jj] = SS[row * 264 + jj * 32 + lane] * scale;
            float m = sv[0];
#pragma unroll
            for (int jj = 1; jj < 8; jj++) m = fmaxf(m, sv[jj]);
#pragma unroll
            for (int off = 16; off > 0; off >>= 1)
                m = fmaxf(m, __shfl_xor_sync(0xffffffffu, m, off));
            float l = 0.f;
#pragma unroll
            for (int jj = 0; jj < 8; jj++) { sv[jj] = __expf(sv[jj] - m); l += sv[jj]; }
#pragma unroll
            for (int off = 16; off > 0; off >>= 1)
                l += __shfl_xor_sync(0xffffffffu, l, off);
            const float inv = 1.f / l;
            const long arow = attn_base + (long)(qc * 32 + row) * 256;
#pragma unroll
            for (int jj = 0; jj < 8; jj++) {
                float p = sv[jj] * inv;
                if (attn) __stcs(attn + arow + jj * 32 + lane, p);
                SS[row * 264 + jj * 32 + lane] = cvt_tf32(p);
            }
        }
        __syncthreads();                               // (3) P ready

        // ---- O partial = P[:, w*32:+32] @ V[w*32:+32, :] ----
        float e[2][4][4];
#pragma unroll
        for (int mm = 0; mm < 2; mm++)
#pragma unroll
            for (int nm = 0; nm < 4; nm++)
#pragma unroll
                for (int q = 0; q < 4; q++) e[mm][nm][q] = 0.f;

#pragma unroll
        for (int ks = 0; ks < 4; ks++) {
            const int kof = w * 32 + ks * 8;
            uint32_t a[2][4];
#pragma unroll
            for (int mm = 0; mm < 2; mm++) {
                const float* p = SS + (mm * 16 + g) * 264 + kof + c;
                a[mm][0] = __float_as_uint(p[0]);
                a[mm][1] = __float_as_uint(p[8 * 264]);
                a[mm][2] = __float_as_uint(p[4]);
                a[mm][3] = __float_as_uint(p[8 * 264 + 4]);
            }
#pragma unroll
            for (int nm = 0; nm < 4; nm++) {
                const float* p = VS + (kof + c) * 40 + nm * 8 + g;
                uint32_t b0 = __float_as_uint(p[0]);
                uint32_t b1 = __float_as_uint(p[4 * 40]);
                mma_tf32(e[0][nm], a[0], b0, b1);
                mma_tf32(e[1][nm], a[1], b0, b1);
            }
        }
        __syncthreads();                               // (4) P reads done

        // partials -> SS as part[w][32][33]
        // NOTE: stride 33 is odd -> odd-row float offsets are only 4B-aligned.
        // Must use scalar stores here (float2 caused 'misaligned address').
#pragma unroll
        for (int mm = 0; mm < 2; mm++)
#pragma unroll
            for (int nm = 0; nm < 4; nm++) {
                const int base = w * 1056 + (mm * 16 + g) * 33 + nm * 8 + 2 * c;
                SS[base]              = e[mm][nm][0];
                SS[base + 1]          = e[mm][nm][1];
                SS[base + 8 * 33]     = e[mm][nm][2];
                SS[base + 8 * 33 + 1] = e[mm][nm][3];
            }
        __syncthreads();                               // (5) partials staged

        // ---- reduce 8 partials, store O (tf32-rounded for proj GEMM) ----
        {
            const int dd = tid & 31;
            const int r0 = (tid >> 5) * 4;
#pragma unroll
            for (int i = 0; i < 4; i++) {
                const int r = r0 + i;
                float acc = 0.f;
#pragma unroll
                for (int wp = 0; wp < 8; wp++)
                    acc += SS[wp * 1056 + r * 33 + dd];
                const int rw = qc * 32 + r;
                const long gtok = tok_base + (long)(rw >> 4) * 256 + (rw & 15);
                o_out[gtok * CDIM + h * HDIM + dd] = cvt_tf32(acc);
            }
        }
        __syncthreads();                               // (6) SS/QS free
    }
}

// ---------------------------------------------------------------------------
extern "C" void kernel_launch(void* const* d_in, const int* in_sizes, int n_in,
                              void* d_out, int out_size)
{
    (void)in_sizes; (void)n_in;
    const float* x      = (const float*)d_in[0];
    const float* qkv_w  = (const float*)d_in[1];
    const float* qkv_b  = (const float*)d_in[2];
    const float* proj_w = (const float*)d_in[3];
    const float* proj_b = (const float*)d_in[4];

    float *qkv_buf, *o_buf, *xt, *wq, *wp;
    cudaGetSymbolAddress((void**)&qkv_buf, g_qkv);
    cudaGetSymbolAddress((void**)&o_buf,   g_o);
    cudaGetSymbolAddress((void**)&xt,      g_xt);
    cudaGetSymbolAddress((void**)&wq,      g_wq);
    cudaGetSymbolAddress((void**)&wp,      g_wp);

    float* out_ptr  = (float*)d_out;
    float* attn_ptr = nullptr;
    long osz = (long)out_size;
    if (osz >= OUT_ELEMS + ATTN_ELEMS) {
        out_ptr  = (float*)d_out;
        attn_ptr = (float*)d_out + OUT_ELEMS;
    } else if (osz == ATTN_ELEMS) {
        attn_ptr = (float*)d_out;
        out_ptr  = qkv_buf;
    }

    // 0) Round inputs/weights to tf32 (rna — zero-mean rounding)
    cvt_tf32_kernel<<<4096, 256>>>(x,      xt, OUT_ELEMS / 4);
    cvt_tf32_kernel<<<192,  256>>>(qkv_w,  wq, (long)(CDIM * QKVN) / 4);
    cvt_tf32_kernel<<<64,   256>>>(proj_w, wp, (long)(CDIM * CDIM) / 4);

    // 1) QKV projection (tf32 mma.sync)
    cudaFuncSetAttribute(sgemm_tf32, cudaFuncAttributeMaxDynamicSharedMemorySize, GEMM_SMEM);
    sgemm_tf32<<<dim3(QKVN / 128, (int)(MROWS / 128)), 256, GEMM_SMEM>>>(
        xt, wq, qkv_b, qkv_buf, QKVN);

    // 2) Windowed attention (tf32 mma.sync)
    cudaFuncSetAttribute(attn_tc, cudaFuncAttributeMaxDynamicSharedMemorySize, AT_BYTES);
    attn_tc<<<NWIN * NHEAD, 256, AT_BYTES>>>(qkv_buf, o_buf, attn_ptr);

    // 3) Output projection (tf32 mma.sync)
    sgemm_tf32<<<dim3(CDIM / 128, (int)(MROWS / 128)), 256, GEMM_SMEM>>>(
        o_buf, wp, proj_b, out_ptr, CDIM);
}